// round 3
// baseline (speedup 1.0000x reference)
#include <cuda_runtime.h>
#include <math.h>
#include <cstdint>

// Real spherical harmonics Y_{l,m}, l_max = 8, output [N, 81] fp32.
// Compute per-thread into smem in OUTPUT order (stride 81, coprime with 32
// banks -> conflict-free STS), then flush the whole contiguous 41,472-byte
// block region with ONE TMA bulk store (cp.async.bulk.global.shared::cta),
// bypassing the LSU/L1 for the entire read+store path.

namespace {
constexpr int LMAX  = 8;
constexpr int NCOLS = (LMAX + 1) * (LMAX + 1);  // 81
constexpr int BLK   = 128;
constexpr int TILE_BYTES = BLK * NCOLS * 4;     // 41472, multiple of 16

struct KTab { float v[LMAX + 1][LMAX + 1]; };

constexpr double cfact(int n) {
    double r = 1.0;
    for (int i = 2; i <= n; ++i) r *= (double)i;
    return r;
}
constexpr double csqrtd(double x) {
    double g = (x > 1.0) ? x : 1.0;
    for (int i = 0; i < 64; ++i) g = 0.5 * (g + x / g);
    return g;
}
constexpr double CPI = 3.14159265358979323846264338327950288;

constexpr KTab makeK() {
    KTab t{};
    for (int l = 0; l <= LMAX; ++l) {
        for (int m = 0; m <= l; ++m) {
            double k = csqrtd(((2.0 * l + 1.0) / (4.0 * CPI)) *
                              (cfact(l - m) / cfact(l + m)));
            if (m > 0) k *= csqrtd(2.0);
            t.v[l][m] = (float)k;
        }
    }
    return t;
}
}  // namespace

__constant__ KTab KT = makeK();

__device__ __forceinline__ uint32_t smem_u32(const void* p) {
    uint32_t a;
    asm("{ .reg .u64 t; cvta.to.shared.u64 t, %1; cvt.u32.u64 %0, t; }"
        : "=r"(a) : "l"(p));
    return a;
}

__global__ void __launch_bounds__(BLK)
sh_kernel(const float* __restrict__ ct_in,
          const float* __restrict__ ph_in,
          float* __restrict__ out, int n)
{
    __shared__ __align__(16) float s[BLK * NCOLS];  // 41472 B, output order

    const int t    = threadIdx.x;
    const int base = blockIdx.x * BLK;
    const int i    = base + t;

    float ct = 0.0f, ph = 0.0f;
    if (i < n) { ct = ct_in[i]; ph = ph_in[i]; }

    float st = sqrtf(fmaxf(1.0f - ct * ct, 0.0f));
    float sp, cp;
    __sincosf(ph, &sp, &cp);

    float* row = s + t * NCOLS;

    float cm  = 1.0f;  // cos(m*phi)
    float smv = 0.0f;  // sin(m*phi)
    float pmm = 1.0f;  // P(m,m)

#pragma unroll
    for (int m = 0; m <= LMAX; ++m) {
        if (m > 0) {
            float c2 = cm * cp - smv * sp;
            float s2 = smv * cp + cm * sp;
            cm = c2; smv = s2;
            pmm *= st * (float)(2 * m - 1);   // P(m,m)
        }

        float Pa = pmm;  // l = m
        {
            const float k = KT.v[m][m];
            const int c0 = m * m + m;
            if (m == 0) {
                row[c0] = k * Pa;
            } else {
                float kp = k * Pa;
                row[c0 + m] = kp * cm;
                row[c0 - m] = kp * smv;
            }
        }

        if (m < LMAX) {
            float Pb = ct * (float)(2 * m + 1) * Pa;  // l = m+1
            {
                const int l  = m + 1;
                const float k = KT.v[l][m];
                const int c0 = l * l + l;
                if (m == 0) {
                    row[c0] = k * Pb;
                } else {
                    float kp = k * Pb;
                    row[c0 + m] = kp * cm;
                    row[c0 - m] = kp * smv;
                }
            }
#pragma unroll
            for (int l = m + 2; l <= LMAX; ++l) {
                float Pc = ((float)(2 * l - 1) * ct * Pb -
                            (float)(l + m - 1) * Pa) * (1.0f / (float)(l - m));
                const float k = KT.v[l][m];
                const int c0 = l * l + l;
                if (m == 0) {
                    row[c0] = k * Pc;
                } else {
                    float kp = k * Pc;
                    row[c0 + m] = kp * cm;
                    row[c0 - m] = kp * smv;
                }
                Pa = Pb; Pb = Pc;
            }
        }
    }

    __syncthreads();

    float* dst = out + (size_t)base * NCOLS;
    int npts = n - base;
    if (npts > BLK) npts = BLK;

    if (npts == BLK) {
        // Make generic-proxy STS visible to the async proxy, then hand the
        // whole contiguous tile to the TMA engine. LSU/L1 never touch it.
        asm volatile("fence.proxy.async.shared::cta;" ::: "memory");
        if (t == 0) {
            uint32_t src = smem_u32(s);
            asm volatile(
                "cp.async.bulk.global.shared::cta.bulk_group [%0], [%1], %2;"
                :: "l"(dst), "r"(src), "n"(TILE_BYTES) : "memory");
            asm volatile("cp.async.bulk.commit_group;" ::: "memory");
            // Wait only for the smem READ side: smem may be re-provisioned to
            // the next block once the engine has consumed it; the global
            // writes drain independently and complete before kernel end.
            asm volatile("cp.async.bulk.wait_group.read 0;" ::: "memory");
        }
        __syncthreads();  // nobody exits (freeing smem) before the read-drain
    } else if (npts > 0) {
        int total = npts * NCOLS;
        for (int f = t; f < total; f += BLK) {
            __stcs(dst + f, s[f]);
        }
    }
}

extern "C" void kernel_launch(void* const* d_in, const int* in_sizes, int n_in,
                              void* d_out, int out_size)
{
    int ia = (n_in >= 3) ? 1 : 0;
    const float* ct = (const float*)d_in[ia];
    const float* ph = (const float*)d_in[ia + 1];

    int n = out_size / NCOLS;
    if (n <= 0) return;

    int grid = (n + BLK - 1) / BLK;
    sh_kernel<<<grid, BLK>>>(ct, ph, (float*)d_out, n);
}

// round 4
// speedup vs baseline: 1.0957x; 1.0957x over previous
#include <cuda_runtime.h>
#include <math.h>

// Real spherical harmonics Y_{l,m}, l_max = 8, output [N, 81] fp32.
// Store-bound. Per-thread compute into smem in OUTPUT order (stride 81 is
// coprime with 32 banks -> conflict-free STS). Warp-local staging: each
// warp's 32 points form a contiguous 2592-float span in smem AND gmem, so
// each warp flushes independently after __syncwarp — no block barrier, no
// compute/store phase coupling.

namespace {
constexpr int LMAX  = 8;
constexpr int NCOLS = (LMAX + 1) * (LMAX + 1);  // 81
constexpr int BLK   = 128;
constexpr int WPTS  = 32;                        // points per warp
constexpr int WSPAN = WPTS * NCOLS;              // 2592 floats
constexpr int WQ    = WSPAN / 4;                 // 648 float4

struct KTab { float v[LMAX + 1][LMAX + 1]; };

constexpr double cfact(int n) {
    double r = 1.0;
    for (int i = 2; i <= n; ++i) r *= (double)i;
    return r;
}
constexpr double csqrtd(double x) {
    double g = (x > 1.0) ? x : 1.0;
    for (int i = 0; i < 64; ++i) g = 0.5 * (g + x / g);
    return g;
}
constexpr double CPI = 3.14159265358979323846264338327950288;

constexpr KTab makeK() {
    KTab t{};
    for (int l = 0; l <= LMAX; ++l) {
        for (int m = 0; m <= l; ++m) {
            double k = csqrtd(((2.0 * l + 1.0) / (4.0 * CPI)) *
                              (cfact(l - m) / cfact(l + m)));
            if (m > 0) k *= csqrtd(2.0);
            t.v[l][m] = (float)k;
        }
    }
    return t;
}
}  // namespace

__constant__ KTab KT = makeK();

__global__ void __launch_bounds__(BLK)
sh_kernel(const float* __restrict__ ct_in,
          const float* __restrict__ ph_in,
          float* __restrict__ out, int n)
{
    __shared__ __align__(16) float s[BLK * NCOLS];  // 41472 B, output order

    const int t    = threadIdx.x;
    const int w    = t >> 5;          // warp id in block
    const int lane = t & 31;
    const int base = blockIdx.x * BLK;
    const int i    = base + t;

    float ct = 0.0f, ph = 0.0f;
    if (i < n) { ct = ct_in[i]; ph = ph_in[i]; }

    float st = sqrtf(fmaxf(1.0f - ct * ct, 0.0f));
    float sp, cp;
    __sincosf(ph, &sp, &cp);

    float* row = s + t * NCOLS;

    float cm  = 1.0f;  // cos(m*phi)
    float smv = 0.0f;  // sin(m*phi)
    float pmm = 1.0f;  // P(m,m)

#pragma unroll
    for (int m = 0; m <= LMAX; ++m) {
        if (m > 0) {
            float c2 = cm * cp - smv * sp;
            float s2 = smv * cp + cm * sp;
            cm = c2; smv = s2;
            pmm *= st * (float)(2 * m - 1);   // P(m,m)
        }

        float Pa = pmm;  // l = m
        {
            const float k = KT.v[m][m];
            const int c0 = m * m + m;
            if (m == 0) {
                row[c0] = k * Pa;
            } else {
                float kp = k * Pa;
                row[c0 + m] = kp * cm;
                row[c0 - m] = kp * smv;
            }
        }

        if (m < LMAX) {
            float Pb = ct * (float)(2 * m + 1) * Pa;  // l = m+1
            {
                const int l  = m + 1;
                const float k = KT.v[l][m];
                const int c0 = l * l + l;
                if (m == 0) {
                    row[c0] = k * Pb;
                } else {
                    float kp = k * Pb;
                    row[c0 + m] = kp * cm;
                    row[c0 - m] = kp * smv;
                }
            }
#pragma unroll
            for (int l = m + 2; l <= LMAX; ++l) {
                float Pc = ((float)(2 * l - 1) * ct * Pb -
                            (float)(l + m - 1) * Pa) * (1.0f / (float)(l - m));
                const float k = KT.v[l][m];
                const int c0 = l * l + l;
                if (m == 0) {
                    row[c0] = k * Pc;
                } else {
                    float kp = k * Pc;
                    row[c0 + m] = kp * cm;
                    row[c0 - m] = kp * smv;
                }
                Pa = Pb; Pb = Pc;
            }
        }
    }

    __syncwarp();

    // Per-warp flush: this warp's span is contiguous in smem and gmem.
    const int wbase = base + w * WPTS;        // first point of this warp
    int npts = n - wbase;
    if (npts > WPTS) npts = WPTS;

    float* dst = out + (size_t)wbase * NCOLS;
    const float* ws = s + (size_t)w * WSPAN;

    if (npts == WPTS) {
        const float4* s4 = reinterpret_cast<const float4*>(ws);
        float4* d4 = reinterpret_cast<float4*>(dst);
        // 648 float4 / 32 lanes = 20.25 -> 20 full rounds + partial
#pragma unroll 5
        for (int q = lane; q < WQ; q += 32) {
            __stcs(d4 + q, s4[q]);
        }
    } else if (npts > 0) {
        int total = npts * NCOLS;
        for (int f = lane; f < total; f += 32) {
            __stcs(dst + f, ws[f]);
        }
    }
}

extern "C" void kernel_launch(void* const* d_in, const int* in_sizes, int n_in,
                              void* d_out, int out_size)
{
    int ia = (n_in >= 3) ? 1 : 0;
    const float* ct = (const float*)d_in[ia];
    const float* ph = (const float*)d_in[ia + 1];

    int n = out_size / NCOLS;
    if (n <= 0) return;

    int grid = (n + BLK - 1) / BLK;
    sh_kernel<<<grid, BLK>>>(ct, ph, (float*)d_out, n);
}